// round 4
// baseline (speedup 1.0000x reference)
#include <cuda_runtime.h>
#include <cuda_bf16.h>
#include <cstdint>

// ======================= constants =======================
#define NH      16
#define NQ      4096
#define NKV     8192
#define HD      128
#define PREFIX  (NKV - NQ)
#define BQ      128           // per CTA (two groups of 64)
#define GQ      64            // q rows per group
#define BK      64
#define THREADS 256
#define LOG2E   1.4426950408889634f
#define SOFT_C  10.0f

// per-group smem layout (bytes); bf16 rows padded to 136 elems (272B)
#define KST     136
#define KROW    (KST * 2)
#define KH_OFF  0
#define KL_OFF  17408
#define VH_OFF  34816
#define VL_OFF  52224
#define MS_OFF  69632
#define MST     68            // mask floats per row (16B-aligned rows)
#define GRP_BYTES (MS_OFF + GQ * MST * 4)      // 87040
#define SMEM_BYTES (2 * GRP_BYTES)             // 174080

// ======================= PTX helpers (base ISA only) =======================
__device__ __forceinline__ uint32_t smem_to_u32(const void* p) {
    uint32_t a;
    asm("{ .reg .u64 t; cvta.to.shared.u64 t, %1; cvt.u32.u64 %0, t; }" : "=r"(a) : "l"(p));
    return a;
}
__device__ __forceinline__ void ldsm_x4(uint32_t addr, uint32_t& r0, uint32_t& r1,
                                        uint32_t& r2, uint32_t& r3) {
    asm volatile("ldmatrix.sync.aligned.m8n8.x4.shared.b16 {%0,%1,%2,%3}, [%4];"
                 : "=r"(r0), "=r"(r1), "=r"(r2), "=r"(r3) : "r"(addr));
}
__device__ __forceinline__ void ldsm_x4_t(uint32_t addr, uint32_t& r0, uint32_t& r1,
                                          uint32_t& r2, uint32_t& r3) {
    asm volatile("ldmatrix.sync.aligned.m8n8.x4.trans.shared.b16 {%0,%1,%2,%3}, [%4];"
                 : "=r"(r0), "=r"(r1), "=r"(r2), "=r"(r3) : "r"(addr));
}
__device__ __forceinline__ void mma_bf16(float* c, const uint32_t* a, uint32_t b0, uint32_t b1) {
    asm volatile("mma.sync.aligned.m16n8k16.row.col.f32.bf16.bf16.f32 "
                 "{%0,%1,%2,%3}, {%4,%5,%6,%7}, {%8,%9}, {%0,%1,%2,%3};"
                 : "+f"(c[0]), "+f"(c[1]), "+f"(c[2]), "+f"(c[3])
                 : "r"(a[0]), "r"(a[1]), "r"(a[2]), "r"(a[3]), "r"(b0), "r"(b1));
}
__device__ __forceinline__ uint32_t packbf(float lo, float hi) {
    uint32_t r;
    asm("cvt.rn.bf16x2.f32 %0, %1, %2;" : "=r"(r) : "f"(hi), "f"(lo));
    return r;
}
__device__ __forceinline__ float ex2f(float x) {
    float r; asm("ex2.approx.f32 %0, %1;" : "=f"(r) : "f"(x)); return r;
}
__device__ __forceinline__ void split2(float a, float b, uint32_t& hi, uint32_t& lo) {
    hi = packbf(a, b);
    float fa = __uint_as_float(hi << 16);
    float fb = __uint_as_float(hi & 0xffff0000u);
    lo = packbf(a - fa, b - fb);
}
#define BAR_SYNC(id) asm volatile("barrier.sync %0, 128;" :: "r"(id) : "memory")
__device__ __forceinline__ void cp_async16(uint32_t dst, const void* src) {
    asm volatile("cp.async.cg.shared.global [%0], [%1], 16;" :: "r"(dst), "l"(src) : "memory");
}
#define CP_ASYNC_COMMIT() asm volatile("cp.async.commit_group;" ::: "memory")
#define CP_ASYNC_WAIT0()  asm volatile("cp.async.wait_group 0;" ::: "memory")

// stage a 64x128 f32 tile -> hi/lo bf16 smem tiles (128 threads, 16 iters)
__device__ __forceinline__ void stage_kv64(const float* __restrict__ gsrc,
                                           char* sh, char* sl, int gtid) {
#pragma unroll
    for (int i = 0; i < 16; i++) {
        int gi  = gtid + i * 128;
        int row = gi >> 5, c4 = (gi & 31) << 2;
        float4 v = *(const float4*)(gsrc + (size_t)row * HD + c4);
        uint32_t h01, l01, h23, l23;
        split2(v.x, v.y, h01, l01);
        split2(v.z, v.w, h23, l23);
        int off = row * KROW + c4 * 2;
        *(uint2*)(sh + off) = make_uint2(h01, h23);
        *(uint2*)(sl + off) = make_uint2(l01, l23);
    }
}

// ======================= kernel =======================
__global__ void __launch_bounds__(THREADS, 1)
fsdpa_mma(const float* __restrict__ Qg, const float* __restrict__ Kg,
          const float* __restrict__ Vg, const float* __restrict__ Mg,
          float* __restrict__ Og)
{
    extern __shared__ char smem_raw[];
    const int tid  = threadIdx.x;
    const int wid  = tid >> 5;
    const int lane = tid & 31;
    const int grp  = wid >> 2;          // 0 or 1
    const int gtid = tid & 127;         // thread within group
    const int gw   = wid & 3;           // warp within group
    const int barid = 1 + grp;
    const int g    = lane >> 2;
    const int t2   = lane & 3;
    const int h    = blockIdx.y;
    const int q0   = (int)(gridDim.x - 1 - blockIdx.x) * BQ;   // longest work first
    const int qbase = q0 + grp * GQ;    // group's first q row
    const int wq   = gw * 16;           // warp's q offset within group

    char* gsm = smem_raw + grp * GRP_BYTES;
    const uint32_t gsmb = smem_to_u32(smem_raw) + grp * GRP_BYTES;

    const float* kb = Kg + (size_t)h * NKV * HD;
    const float* vb = Vg + (size_t)h * NKV * HD;

    // ---- stage group's Q (scale folded) into K scratch, ldmatrix to regs ----
    {
        const float scale = 0.08838834764831845f;   // 1/sqrt(128)
        const float* qb = Qg + ((size_t)h * NQ + qbase) * HD;
#pragma unroll
        for (int i = 0; i < 16; i++) {
            int gi  = gtid + i * 128;
            int row = gi >> 5, c4 = (gi & 31) << 2;
            float4 v = *(const float4*)(qb + (size_t)row * HD + c4);
            v.x *= scale; v.y *= scale; v.z *= scale; v.w *= scale;
            uint32_t h01, l01, h23, l23;
            split2(v.x, v.y, h01, l01);
            split2(v.z, v.w, h23, l23);
            int off = row * KROW + c4 * 2;
            *(uint2*)(gsm + KH_OFF + off) = make_uint2(h01, h23);
            *(uint2*)(gsm + KL_OFF + off) = make_uint2(l01, l23);
        }
    }
    BAR_SYNC(barid);

    uint32_t qh[8][4], ql[8][4];
    {
        const int mi = lane >> 3;
        const uint32_t ro = (uint32_t)(wq + (lane & 7) + ((mi & 1) << 3)) * KROW + ((mi >> 1) << 4);
#pragma unroll
        for (int kc = 0; kc < 8; kc++) {
            ldsm_x4(gsmb + KH_OFF + ro + kc * 32, qh[kc][0], qh[kc][1], qh[kc][2], qh[kc][3]);
            ldsm_x4(gsmb + KL_OFF + ro + kc * 32, ql[kc][0], ql[kc][1], ql[kc][2], ql[kc][3]);
        }
    }
    BAR_SYNC(barid);

    float o[16][4];
#pragma unroll
    for (int i = 0; i < 16; i++)
#pragma unroll
        for (int j = 0; j < 4; j++) o[i][j] = 0.0f;
    float ls0 = 0.0f, ls1 = 0.0f;

    const int ntiles = (PREFIX + qbase + GQ) / BK;   // group-exact tile count
    float* msf = (float*)(gsm + MS_OFF);
    const float zb = -SOFT_C * LOG2E;

    for (int t = 0; t < ntiles; t++) {
        const int kv0 = t * BK;

        // ---- mask tile via cp.async (prefetch before K/V conversion work) ----
#pragma unroll
        for (int i = 0; i < 8; i++) {
            int gi  = gtid + i * 128;
            int row = gi >> 4, c4 = (gi & 15) << 2;
            cp_async16(gsmb + MS_OFF + (uint32_t)(row * MST + c4) * 4,
                       Mg + (size_t)(qbase + row) * NKV + kv0 + c4);
        }
        CP_ASYNC_COMMIT();

        // ---- stage K, V (hi/lo bf16) ----
        stage_kv64(kb + (size_t)kv0 * HD, gsm + KH_OFF, gsm + KL_OFF, gtid);
        stage_kv64(vb + (size_t)kv0 * HD, gsm + VH_OFF, gsm + VL_OFF, gtid);
        CP_ASYNC_WAIT0();
        BAR_SYNC(barid);

        // ---- S = Q @ K^T (3-term bf16 split) ----
        float s[8][4];
#pragma unroll
        for (int i = 0; i < 8; i++)
#pragma unroll
            for (int j = 0; j < 4; j++) s[i][j] = 0.0f;

#pragma unroll
        for (int nt = 0; nt < 8; nt++) {
            const uint32_t rb = (uint32_t)(nt * 8 + (lane & 7)) * KROW + ((lane >> 3) << 4);
#pragma unroll
            for (int kcp = 0; kcp < 4; kcp++) {
                uint32_t bh0, bh1, bh2, bh3, bl0, bl1, bl2, bl3;
                ldsm_x4(gsmb + KH_OFF + rb + kcp * 64, bh0, bh1, bh2, bh3);
                ldsm_x4(gsmb + KL_OFF + rb + kcp * 64, bl0, bl1, bl2, bl3);
                const int kc = 2 * kcp;
                mma_bf16(s[nt], qh[kc],     bh0, bh1);
                mma_bf16(s[nt], qh[kc],     bl0, bl1);
                mma_bf16(s[nt], ql[kc],     bh0, bh1);
                mma_bf16(s[nt], qh[kc + 1], bh2, bh3);
                mma_bf16(s[nt], qh[kc + 1], bl2, bl3);
                mma_bf16(s[nt], ql[kc + 1], bh2, bh3);
            }
        }

        // ---- softmax: p = exp2((s+mask)*log2e - C*log2e), fixed shift ----
        const int  lim0 = PREFIX + qbase + wq + g - kv0;
        const int  lim1 = lim0 + 8;
        const bool dg   = (t >= ntiles - 2);
        const float* mrow0 = msf + (wq + g) * MST;
        const float* mrow1 = mrow0 + 8 * MST;
#pragma unroll
        for (int nt = 0; nt < 8; nt++) {
            const int c = nt * 8 + t2 * 2;
            float2 m0 = *(const float2*)(mrow0 + c);
            float2 m1 = *(const float2*)(mrow1 + c);
            float z00 = fmaf(s[nt][0] + m0.x, LOG2E, zb);
            float z01 = fmaf(s[nt][1] + m0.y, LOG2E, zb);
            float z10 = fmaf(s[nt][2] + m1.x, LOG2E, zb);
            float z11 = fmaf(s[nt][3] + m1.y, LOG2E, zb);
            if (dg) {
                if (c     > lim0) z00 = -127.0f;
                if (c + 1 > lim0) z01 = -127.0f;
                if (c     > lim1) z10 = -127.0f;
                if (c + 1 > lim1) z11 = -127.0f;
            }
            float p00 = ex2f(z00), p01 = ex2f(z01);
            float p10 = ex2f(z10), p11 = ex2f(z11);
            ls0 += p00 + p01;
            ls1 += p10 + p11;
            s[nt][0] = p00; s[nt][1] = p01; s[nt][2] = p10; s[nt][3] = p11;
        }

        // ---- O += P @ V (3-term bf16 split, V via ldmatrix.trans) ----
#pragma unroll
        for (int kc = 0; kc < 4; kc++) {
            uint32_t ah[4], al[4];
            split2(s[2 * kc][0],     s[2 * kc][1],     ah[0], al[0]);
            split2(s[2 * kc][2],     s[2 * kc][3],     ah[1], al[1]);
            split2(s[2 * kc + 1][0], s[2 * kc + 1][1], ah[2], al[2]);
            split2(s[2 * kc + 1][2], s[2 * kc + 1][3], ah[3], al[3]);
            const uint32_t rv = (uint32_t)(kc * 16 + ((lane >> 3) & 1) * 8 + (lane & 7)) * KROW
                              + ((lane >> 4) << 4);
#pragma unroll
            for (int ntp = 0; ntp < 8; ntp++) {
                uint32_t vh0, vh1, vh2, vh3, vl0, vl1, vl2, vl3;
                ldsm_x4_t(gsmb + VH_OFF + rv + ntp * 32, vh0, vh1, vh2, vh3);
                ldsm_x4_t(gsmb + VL_OFF + rv + ntp * 32, vl0, vl1, vl2, vl3);
                mma_bf16(o[2 * ntp],     ah, vh0, vh1);
                mma_bf16(o[2 * ntp],     ah, vl0, vl1);
                mma_bf16(o[2 * ntp],     al, vh0, vh1);
                mma_bf16(o[2 * ntp + 1], ah, vh2, vh3);
                mma_bf16(o[2 * ntp + 1], ah, vl2, vl3);
                mma_bf16(o[2 * ntp + 1], al, vh2, vh3);
            }
        }
        BAR_SYNC(barid);
    }

    // ---- epilogue: reduce lsum over the quad, divide, store ----
    ls0 += __shfl_xor_sync(0xffffffffu, ls0, 1);
    ls0 += __shfl_xor_sync(0xffffffffu, ls0, 2);
    ls1 += __shfl_xor_sync(0xffffffffu, ls1, 1);
    ls1 += __shfl_xor_sync(0xffffffffu, ls1, 2);
    const float i0 = 1.0f / ls0;
    const float i1 = 1.0f / ls1;

    float* ob = Og + ((size_t)h * NQ + qbase + wq) * HD;
#pragma unroll
    for (int nt = 0; nt < 16; nt++) {
        const int c = nt * 8 + t2 * 2;
        float2 w0 = make_float2(o[nt][0] * i0, o[nt][1] * i0);
        float2 w1 = make_float2(o[nt][2] * i1, o[nt][3] * i1);
        *(float2*)(ob + (size_t)g * HD + c)       = w0;
        *(float2*)(ob + (size_t)(g + 8) * HD + c) = w1;
    }
}

extern "C" void kernel_launch(void* const* d_in, const int* in_sizes, int n_in,
                              void* d_out, int out_size)
{
    const float* q = (const float*)d_in[0];
    const float* k = (const float*)d_in[1];
    const float* v = (const float*)d_in[2];
    const float* m = (const float*)d_in[3];
    float* o = (float*)d_out;

    cudaFuncSetAttribute(fsdpa_mma, cudaFuncAttributeMaxDynamicSharedMemorySize, SMEM_BYTES);
    dim3 grid(NQ / BQ, NH);
    fsdpa_mma<<<grid, THREADS, SMEM_BYTES>>>(q, k, v, m, o);
}

// round 6
// speedup vs baseline: 1.1985x; 1.1985x over previous
#include <cuda_runtime.h>
#include <cuda_bf16.h>
#include <cstdint>

// ======================= constants =======================
#define NH      16
#define NQ      4096
#define NKV     8192
#define HD      128
#define PREFIX  (NKV - NQ)
#define BQ      128
#define BK      64
#define THREADS 256
#define LOG2E   1.4426950408889634f
#define SOFT_C  10.0f

// bf16 tiles: 64 rows x 128 elems, row stride 272B (+16B pad, ldsm conflict-free)
#define KROW    272
#define KTILE   17408              // 64*272
// smem layout (bytes)
#define KBH(b)  ((b) * 34816)      // K hi bf16, double buffered
#define KBL(b)  ((b) * 34816 + KTILE)
#define VBH     69632
#define VBL     87040
#define KF      104448             // K f32 staging (64 x 512B)
#define VF      137216             // V f32 staging
#define MS      169984             // mask f32 (128 rows x 256B)
#define SMEM_BYTES 202752
// Q staging scratch (dead regions at prologue time):
//   Q-hi rows 0..127 -> [0, 34816)        (KBH(0)+KBL(0))
//   Q-lo rows 0..127 -> [69632, 104448)   (VBH+VBL)
#define QSH     0
#define QSL     VBH

// ======================= PTX helpers (base ISA only) =======================
__device__ __forceinline__ uint32_t smem_to_u32(const void* p) {
    uint32_t a;
    asm("{ .reg .u64 t; cvta.to.shared.u64 t, %1; cvt.u32.u64 %0, t; }" : "=r"(a) : "l"(p));
    return a;
}
__device__ __forceinline__ void ldsm_x4(uint32_t addr, uint32_t& r0, uint32_t& r1,
                                        uint32_t& r2, uint32_t& r3) {
    asm volatile("ldmatrix.sync.aligned.m8n8.x4.shared.b16 {%0,%1,%2,%3}, [%4];"
                 : "=r"(r0), "=r"(r1), "=r"(r2), "=r"(r3) : "r"(addr));
}
__device__ __forceinline__ void ldsm_x4_t(uint32_t addr, uint32_t& r0, uint32_t& r1,
                                          uint32_t& r2, uint32_t& r3) {
    asm volatile("ldmatrix.sync.aligned.m8n8.x4.trans.shared.b16 {%0,%1,%2,%3}, [%4];"
                 : "=r"(r0), "=r"(r1), "=r"(r2), "=r"(r3) : "r"(addr));
}
__device__ __forceinline__ void mma_bf16(float* c, const uint32_t* a, uint32_t b0, uint32_t b1) {
    asm volatile("mma.sync.aligned.m16n8k16.row.col.f32.bf16.bf16.f32 "
                 "{%0,%1,%2,%3}, {%4,%5,%6,%7}, {%8,%9}, {%0,%1,%2,%3};"
                 : "+f"(c[0]), "+f"(c[1]), "+f"(c[2]), "+f"(c[3])
                 : "r"(a[0]), "r"(a[1]), "r"(a[2]), "r"(a[3]), "r"(b0), "r"(b1));
}
__device__ __forceinline__ uint32_t packbf(float lo, float hi) {
    uint32_t r;
    asm("cvt.rn.bf16x2.f32 %0, %1, %2;" : "=r"(r) : "f"(hi), "f"(lo));
    return r;
}
__device__ __forceinline__ float ex2f(float x) {
    float r; asm("ex2.approx.f32 %0, %1;" : "=f"(r) : "f"(x)); return r;
}
__device__ __forceinline__ void split2(float a, float b, uint32_t& hi, uint32_t& lo) {
    hi = packbf(a, b);
    float fa = __uint_as_float(hi << 16);
    float fb = __uint_as_float(hi & 0xffff0000u);
    lo = packbf(a - fa, b - fb);
}
__device__ __forceinline__ void cp_async16(uint32_t dst, const void* src) {
    asm volatile("cp.async.cg.shared.global [%0], [%1], 16;" :: "r"(dst), "l"(src) : "memory");
}
#define CP_COMMIT() asm volatile("cp.async.commit_group;" ::: "memory")
#define CP_WAIT(n)  asm volatile("cp.async.wait_group %0;" :: "n"(n) : "memory")

// convert one f32 row (512B) to bf16 hi/lo row; whole warp, 4 floats/lane
__device__ __forceinline__ void conv_row(const char* smem, int f32_off, int hi_off,
                                         int lo_off, int row, int lane) {
    float4 v = *(const float4*)(smem + f32_off + row * 512 + lane * 16);
    uint32_t h01, l01, h23, l23;
    split2(v.x, v.y, h01, l01);
    split2(v.z, v.w, h23, l23);
    int off = row * KROW + lane * 8;
    *(uint2*)(const_cast<char*>(smem) + hi_off + off) = make_uint2(h01, h23);
    *(uint2*)(const_cast<char*>(smem) + lo_off + off) = make_uint2(l01, l23);
}

// ======================= kernel =======================
__global__ void __launch_bounds__(THREADS, 1)
fsdpa_mma(const float* __restrict__ Qg, const float* __restrict__ Kg,
          const float* __restrict__ Vg, const float* __restrict__ Mg,
          float* __restrict__ Og)
{
    extern __shared__ char smem[];
    const uint32_t smb = smem_to_u32(smem);
    const int tid  = threadIdx.x;
    const int wid  = tid >> 5;
    const int lane = tid & 31;
    const int g    = lane >> 2;
    const int t2   = lane & 3;
    const int h    = blockIdx.y;
    const int q0   = (int)(gridDim.x - 1 - blockIdx.x) * BQ;  // longest work first
    const int wq   = wid * 16;

    const float* kb = Kg + (size_t)h * NKV * HD;
    const float* vb = Vg + (size_t)h * NKV * HD;
    const int ntiles = (PREFIX + q0 + BQ) / BK;

    // ---- prologue: prefetch tile 0 (group1: K+mask, group2: V) ----
#pragma unroll
    for (int i = 0; i < 8; i++) {
        int gi = tid + i * THREADS;
        int row = gi >> 5, c4 = gi & 31;
        cp_async16(smb + KF + row * 512 + c4 * 16, kb + (size_t)row * HD + c4 * 4);
    }
#pragma unroll
    for (int i = 0; i < 8; i++) {
        int gi = tid + i * THREADS;
        int row = gi >> 4, c4 = gi & 15;
        cp_async16(smb + MS + row * 256 + c4 * 16, Mg + (size_t)(q0 + row) * NKV + c4 * 4);
    }
    CP_COMMIT();
#pragma unroll
    for (int i = 0; i < 8; i++) {
        int gi = tid + i * THREADS;
        int row = gi >> 5, c4 = gi & 31;
        cp_async16(smb + VF + row * 512 + c4 * 16, vb + (size_t)row * HD + c4 * 4);
    }
    CP_COMMIT();

    // ---- stage Q (scale folded) into non-overlapping scratch, ldmatrix to regs ----
    {
        const float scale = 0.08838834764831845f;   // 1/sqrt(128)
        const float* qb = Qg + ((size_t)h * NQ + q0) * HD;
#pragma unroll
        for (int i = 0; i < 16; i++) {
            int gi  = tid + i * THREADS;
            int row = gi >> 5, c4 = (gi & 31) << 2;
            float4 v = *(const float4*)(qb + (size_t)row * HD + c4);
            v.x *= scale; v.y *= scale; v.z *= scale; v.w *= scale;
            uint32_t h01, l01, h23, l23;
            split2(v.x, v.y, h01, l01);
            split2(v.z, v.w, h23, l23);
            int off = row * KROW + c4 * 2;
            *(uint2*)(smem + QSH + off) = make_uint2(h01, h23);
            *(uint2*)(smem + QSL + off) = make_uint2(l01, l23);
        }
    }
    __syncthreads();

    uint32_t qh[8][4], ql[8][4];
    {
        const int mi = lane >> 3;
        const uint32_t ro = (uint32_t)(wq + (lane & 7) + ((mi & 1) << 3)) * KROW + ((mi >> 1) << 4);
#pragma unroll
        for (int kc = 0; kc < 8; kc++) {
            ldsm_x4(smb + QSH + ro + kc * 32, qh[kc][0], qh[kc][1], qh[kc][2], qh[kc][3]);
            ldsm_x4(smb + QSL + ro + kc * 32, ql[kc][0], ql[kc][1], ql[kc][2], ql[kc][3]);
        }
    }
    __syncthreads();   // Q in regs; scratch (KBH(0)/KBL(0), VBH/VBL) may be reused now

    // ---- convert K(0) -> KBH(0)/KBL(0) (shared across 256 threads) ----
    CP_WAIT(1);
    __syncthreads();
#pragma unroll
    for (int i = 0; i < 8; i++) {
        int gi = tid + i * THREADS;
        conv_row(smem, KF, KBH(0), KBL(0), gi >> 5, gi & 31);
    }
    CP_WAIT(0);
    __syncthreads();

    float o[16][4];
#pragma unroll
    for (int i = 0; i < 16; i++)
#pragma unroll
        for (int j = 0; j < 4; j++) o[i][j] = 0.0f;
    float ls0 = 0.0f, ls1 = 0.0f;

    float* msf = (float*)(smem + MS);
    const float zb = -SOFT_C * LOG2E;

    for (int t = 0; t < ntiles; t++) {
        const int kv0 = t * BK;
        const int kv1 = kv0 + BK;
        const bool more = (t + 1 < ntiles);
        const int kbh = KBH(t & 1), kbl = kbh + KTILE;
        const int nbh = KBH((t + 1) & 1), nbl = nbh + KTILE;

        // step0: prefetch K f32(t+1)
        if (more) {
#pragma unroll
            for (int i = 0; i < 8; i++) {
                int gi = tid + i * THREADS;
                int row = gi >> 5, c4 = gi & 31;
                cp_async16(smb + KF + row * 512 + c4 * 16,
                           kb + (size_t)(kv1 + row) * HD + c4 * 4);
            }
        }
        CP_COMMIT();

        // step1: S = Q @ K^T with embedded convert-V(t) chunks
        float s[8][4];
#pragma unroll
        for (int i = 0; i < 8; i++)
#pragma unroll
            for (int j = 0; j < 4; j++) s[i][j] = 0.0f;

#pragma unroll
        for (int nt = 0; nt < 8; nt++) {
            conv_row(smem, VF, VBH, VBL, wid * 8 + nt, lane);   // V f32 -> bf16 (1 row/warp)
            const uint32_t rb = (uint32_t)(nt * 8 + (lane & 7)) * KROW + ((lane >> 3) << 4);
#pragma unroll
            for (int kcp = 0; kcp < 4; kcp++) {
                uint32_t bh0, bh1, bh2, bh3, bl0, bl1, bl2, bl3;
                ldsm_x4(smb + kbh + rb + kcp * 64, bh0, bh1, bh2, bh3);
                ldsm_x4(smb + kbl + rb + kcp * 64, bl0, bl1, bl2, bl3);
                const int kc = 2 * kcp;
                mma_bf16(s[nt], qh[kc],     bh0, bh1);
                mma_bf16(s[nt], qh[kc],     bl0, bl1);
                mma_bf16(s[nt], ql[kc],     bh0, bh1);
                mma_bf16(s[nt], qh[kc + 1], bh2, bh3);
                mma_bf16(s[nt], qh[kc + 1], bl2, bl3);
                mma_bf16(s[nt], ql[kc + 1], bh2, bh3);
            }
        }

        // step2: softmax (fixed-shift), mask from smem
        {
            const int  lim0 = PREFIX + q0 + wq + g - kv0;
            const int  lim1 = lim0 + 8;
            const bool dg   = (t >= ntiles - 2);
            const float* mrow0 = msf + (wq + g) * 64;
            const float* mrow1 = mrow0 + 8 * 64;
#pragma unroll
            for (int nt = 0; nt < 8; nt++) {
                const int c = nt * 8 + t2 * 2;
                float2 m0 = *(const float2*)(mrow0 + c);
                float2 m1 = *(const float2*)(mrow1 + c);
                float z00 = fmaf(s[nt][0] + m0.x, LOG2E, zb);
                float z01 = fmaf(s[nt][1] + m0.y, LOG2E, zb);
                float z10 = fmaf(s[nt][2] + m1.x, LOG2E, zb);
                float z11 = fmaf(s[nt][3] + m1.y, LOG2E, zb);
                if (dg) {
                    if (c     > lim0) z00 = -127.0f;
                    if (c + 1 > lim0) z01 = -127.0f;
                    if (c     > lim1) z10 = -127.0f;
                    if (c + 1 > lim1) z11 = -127.0f;
                }
                float p00 = ex2f(z00), p01 = ex2f(z01);
                float p10 = ex2f(z10), p11 = ex2f(z11);
                ls0 += p00 + p01;
                ls1 += p10 + p11;
                s[nt][0] = p00; s[nt][1] = p01; s[nt][2] = p10; s[nt][3] = p11;
            }
        }

        // step3: all warps done with V f32(t) chunks + mask(t)
        __syncthreads();

        // step4: prefetch V f32(t+1) + mask(t+1)
        if (more) {
#pragma unroll
            for (int i = 0; i < 8; i++) {
                int gi = tid + i * THREADS;
                int row = gi >> 5, c4 = gi & 31;
                cp_async16(smb + VF + row * 512 + c4 * 16,
                           vb + (size_t)(kv1 + row) * HD + c4 * 4);
            }
#pragma unroll
            for (int i = 0; i < 8; i++) {
                int gi = tid + i * THREADS;
                int row = gi >> 4, c4 = gi & 15;
                cp_async16(smb + MS + row * 256 + c4 * 16,
                           Mg + (size_t)(q0 + row) * NKV + kv1 + c4 * 4);
            }
        }
        CP_COMMIT();

        // step5/6: K f32(t+1) arrived; publish
        CP_WAIT(1);
        __syncthreads();

        // step7: O += P @ V with embedded convert-K(t+1) chunks
#pragma unroll
        for (int kc = 0; kc < 4; kc++) {
            if (more) {
                conv_row(smem, KF, nbh, nbl, wid * 8 + kc * 2,     lane);
                conv_row(smem, KF, nbh, nbl, wid * 8 + kc * 2 + 1, lane);
            }
            uint32_t ah[4], al[4];
            split2(s[2 * kc][0],     s[2 * kc][1],     ah[0], al[0]);
            split2(s[2 * kc][2],     s[2 * kc][3],     ah[1], al[1]);
            split2(s[2 * kc + 1][0], s[2 * kc + 1][1], ah[2], al[2]);
            split2(s[2 * kc + 1][2], s[2 * kc + 1][3], ah[3], al[3]);
            const uint32_t rv = (uint32_t)(kc * 16 + ((lane >> 3) & 1) * 8 + (lane & 7)) * KROW
                              + ((lane >> 4) << 4);
#pragma unroll
            for (int ntp = 0; ntp < 8; ntp++) {
                uint32_t vh0, vh1, vh2, vh3, vl0, vl1, vl2, vl3;
                ldsm_x4_t(smb + VBH + rv + ntp * 32, vh0, vh1, vh2, vh3);
                ldsm_x4_t(smb + VBL + rv + ntp * 32, vl0, vl1, vl2, vl3);
                mma_bf16(o[2 * ntp],     ah, vh0, vh1);
                mma_bf16(o[2 * ntp],     ah, vl0, vl1);
                mma_bf16(o[2 * ntp],     al, vh0, vh1);
                mma_bf16(o[2 * ntp + 1], ah, vh2, vh3);
                mma_bf16(o[2 * ntp + 1], ah, vl2, vl3);
                mma_bf16(o[2 * ntp + 1], al, vh2, vh3);
            }
        }

        // step8/9: V+mask(t+1) arrived; close tile
        CP_WAIT(0);
        __syncthreads();
    }

    // ---- epilogue ----
    ls0 += __shfl_xor_sync(0xffffffffu, ls0, 1);
    ls0 += __shfl_xor_sync(0xffffffffu, ls0, 2);
    ls1 += __shfl_xor_sync(0xffffffffu, ls1, 1);
    ls1 += __shfl_xor_sync(0xffffffffu, ls1, 2);
    const float i0 = 1.0f / ls0;
    const float i1 = 1.0f / ls1;

    float* ob = Og + ((size_t)h * NQ + q0 + wq) * HD;
#pragma unroll
    for (int nt = 0; nt < 16; nt++) {
        const int c = nt * 8 + t2 * 2;
        float2 w0 = make_float2(o[nt][0] * i0, o[nt][1] * i0);
        float2 w1 = make_float2(o[nt][2] * i1, o[nt][3] * i1);
        *(float2*)(ob + (size_t)g * HD + c)       = w0;
        *(float2*)(ob + (size_t)(g + 8) * HD + c) = w1;
    }
}

extern "C" void kernel_launch(void* const* d_in, const int* in_sizes, int n_in,
                              void* d_out, int out_size)
{
    const float* q = (const float*)d_in[0];
    const float* k = (const float*)d_in[1];
    const float* v = (const float*)d_in[2];
    const float* m = (const float*)d_in[3];
    float* o = (float*)d_out;

    cudaFuncSetAttribute(fsdpa_mma, cudaFuncAttributeMaxDynamicSharedMemorySize, SMEM_BYTES);
    dim3 grid(NQ / BQ, NH);
    fsdpa_mma<<<grid, THREADS, SMEM_BYTES>>>(q, k, v, m, o);
}

// round 7
// speedup vs baseline: 1.2916x; 1.0777x over previous
#include <cuda_runtime.h>
#include <cuda_bf16.h>
#include <cstdint>

// ======================= constants =======================
#define NH      16
#define NQ      4096
#define NKV     8192
#define HD      128
#define PREFIX  (NKV - NQ)
#define BQ      128
#define BK      64
#define THREADS 256
#define LOG2E   1.4426950408889634f
#define SOFT_C  10.0f

// bf16 tiles: 64 rows x 128 elems, row stride 272B (+16B pad, ldsm conflict-free)
#define KROW    272
#define KTILE   17408              // 64*272
// smem layout (bytes)
#define KBH(b)  ((b) * 34816)      // K hi bf16, double buffered
#define KBL(b)  ((b) * 34816 + KTILE)
#define VBH     69632
#define VBL     87040
#define KF      104448             // K f32 staging (64 x 512B)
#define VF      137216             // V f32 staging
#define MS      169984             // mask f32 (128 rows x 256B)
#define SMEM_BYTES 202752
// Q staging scratch (dead regions at prologue time):
#define QSH     0
#define QSL     VBH

// ======================= PTX helpers (base ISA only) =======================
__device__ __forceinline__ uint32_t smem_to_u32(const void* p) {
    uint32_t a;
    asm("{ .reg .u64 t; cvta.to.shared.u64 t, %1; cvt.u32.u64 %0, t; }" : "=r"(a) : "l"(p));
    return a;
}
__device__ __forceinline__ void ldsm_x4(uint32_t addr, uint32_t& r0, uint32_t& r1,
                                        uint32_t& r2, uint32_t& r3) {
    asm volatile("ldmatrix.sync.aligned.m8n8.x4.shared.b16 {%0,%1,%2,%3}, [%4];"
                 : "=r"(r0), "=r"(r1), "=r"(r2), "=r"(r3) : "r"(addr));
}
__device__ __forceinline__ void ldsm_x4_t(uint32_t addr, uint32_t& r0, uint32_t& r1,
                                          uint32_t& r2, uint32_t& r3) {
    asm volatile("ldmatrix.sync.aligned.m8n8.x4.trans.shared.b16 {%0,%1,%2,%3}, [%4];"
                 : "=r"(r0), "=r"(r1), "=r"(r2), "=r"(r3) : "r"(addr));
}
__device__ __forceinline__ void mma_bf16(float* c, const uint32_t* a, uint32_t b0, uint32_t b1) {
    asm volatile("mma.sync.aligned.m16n8k16.row.col.f32.bf16.bf16.f32 "
                 "{%0,%1,%2,%3}, {%4,%5,%6,%7}, {%8,%9}, {%0,%1,%2,%3};"
                 : "+f"(c[0]), "+f"(c[1]), "+f"(c[2]), "+f"(c[3])
                 : "r"(a[0]), "r"(a[1]), "r"(a[2]), "r"(a[3]), "r"(b0), "r"(b1));
}
__device__ __forceinline__ uint32_t packbf(float lo, float hi) {
    uint32_t r;
    asm("cvt.rn.bf16x2.f32 %0, %1, %2;" : "=r"(r) : "f"(hi), "f"(lo));
    return r;
}
__device__ __forceinline__ float ex2f(float x) {
    float r; asm("ex2.approx.f32 %0, %1;" : "=f"(r) : "f"(x)); return r;
}
__device__ __forceinline__ void split2(float a, float b, uint32_t& hi, uint32_t& lo) {
    hi = packbf(a, b);
    float fa = __uint_as_float(hi << 16);
    float fb = __uint_as_float(hi & 0xffff0000u);
    lo = packbf(a - fa, b - fb);
}
__device__ __forceinline__ void cp_async16(uint32_t dst, const void* src) {
    asm volatile("cp.async.cg.shared.global [%0], [%1], 16;" :: "r"(dst), "l"(src) : "memory");
}
#define CP_COMMIT() asm volatile("cp.async.commit_group;" ::: "memory")
#define CP_WAIT(n)  asm volatile("cp.async.wait_group %0;" :: "n"(n) : "memory")

// convert one f32 row (512B) to bf16 hi/lo row; whole warp, 4 floats/lane
__device__ __forceinline__ void conv_row(const char* smem, int f32_off, int hi_off,
                                         int lo_off, int row, int lane) {
    float4 v = *(const float4*)(smem + f32_off + row * 512 + lane * 16);
    uint32_t h01, l01, h23, l23;
    split2(v.x, v.y, h01, l01);
    split2(v.z, v.w, h23, l23);
    int off = row * KROW + lane * 8;
    *(uint2*)(const_cast<char*>(smem) + hi_off + off) = make_uint2(h01, h23);
    *(uint2*)(const_cast<char*>(smem) + lo_off + off) = make_uint2(l01, l23);
}

// ======================= kernel =======================
__global__ void __launch_bounds__(THREADS, 1)
fsdpa_mma(const float* __restrict__ Qg, const float* __restrict__ Kg,
          const float* __restrict__ Vg, const float* __restrict__ Mg,
          float* __restrict__ Og)
{
    extern __shared__ char smem[];
    const uint32_t smb = smem_to_u32(smem);
    const int tid  = threadIdx.x;
    const int wid  = tid >> 5;
    const int lane = tid & 31;
    const int g    = lane >> 2;
    const int t2   = lane & 3;
    const int h    = blockIdx.y;
    const int q0   = (int)(gridDim.x - 1 - blockIdx.x) * BQ;  // longest work first
    const int wq   = wid * 16;

    const float* kb = Kg + (size_t)h * NKV * HD;
    const float* vb = Vg + (size_t)h * NKV * HD;
    const int ntiles = (PREFIX + q0 + BQ) / BK;

    // ---- prologue: prefetch tile 0 (group1: K+mask, group2: V) ----
#pragma unroll
    for (int i = 0; i < 8; i++) {
        int gi = tid + i * THREADS;
        int row = gi >> 5, c4 = gi & 31;
        cp_async16(smb + KF + row * 512 + c4 * 16, kb + (size_t)row * HD + c4 * 4);
    }
#pragma unroll
    for (int i = 0; i < 8; i++) {
        int gi = tid + i * THREADS;
        int row = gi >> 4, c4 = gi & 15;
        cp_async16(smb + MS + row * 256 + c4 * 16, Mg + (size_t)(q0 + row) * NKV + c4 * 4);
    }
    CP_COMMIT();
#pragma unroll
    for (int i = 0; i < 8; i++) {
        int gi = tid + i * THREADS;
        int row = gi >> 5, c4 = gi & 31;
        cp_async16(smb + VF + row * 512 + c4 * 16, vb + (size_t)row * HD + c4 * 4);
    }
    CP_COMMIT();

    // ---- stage Q (scale folded) into non-overlapping scratch, ldmatrix to regs ----
    {
        const float scale = 0.08838834764831845f;   // 1/sqrt(128)
        const float* qb = Qg + ((size_t)h * NQ + q0) * HD;
#pragma unroll
        for (int i = 0; i < 16; i++) {
            int gi  = tid + i * THREADS;
            int row = gi >> 5, c4 = (gi & 31) << 2;
            float4 v = *(const float4*)(qb + (size_t)row * HD + c4);
            v.x *= scale; v.y *= scale; v.z *= scale; v.w *= scale;
            uint32_t h01, l01, h23, l23;
            split2(v.x, v.y, h01, l01);
            split2(v.z, v.w, h23, l23);
            int off = row * KROW + c4 * 2;
            *(uint2*)(smem + QSH + off) = make_uint2(h01, h23);
            *(uint2*)(smem + QSL + off) = make_uint2(l01, l23);
        }
    }
    __syncthreads();

    uint32_t qh[8][4], ql[8][4];
    {
        const int mi = lane >> 3;
        const uint32_t ro = (uint32_t)(wq + (lane & 7) + ((mi & 1) << 3)) * KROW + ((mi >> 1) << 4);
#pragma unroll
        for (int kc = 0; kc < 8; kc++) {
            ldsm_x4(smb + QSH + ro + kc * 32, qh[kc][0], qh[kc][1], qh[kc][2], qh[kc][3]);
            ldsm_x4(smb + QSL + ro + kc * 32, ql[kc][0], ql[kc][1], ql[kc][2], ql[kc][3]);
        }
    }
    __syncthreads();   // Q in regs; scratch may be reused now

    // ---- convert K(0) -> KBH(0)/KBL(0) (shared across 256 threads) ----
    CP_WAIT(1);
    __syncthreads();
#pragma unroll
    for (int i = 0; i < 8; i++) {
        int gi = tid + i * THREADS;
        conv_row(smem, KF, KBH(0), KBL(0), gi >> 5, gi & 31);
    }
    CP_WAIT(0);
    __syncthreads();

    float o[16][4];
#pragma unroll
    for (int i = 0; i < 16; i++)
#pragma unroll
        for (int j = 0; j < 4; j++) o[i][j] = 0.0f;
    float ls0 = 0.0f, ls1 = 0.0f;

    float* msf = (float*)(smem + MS);
    const float zb = -SOFT_C * LOG2E;

    for (int t = 0; t < ntiles; t++) {
        const int kv0 = t * BK;
        const int kv1 = kv0 + BK;
        const bool more = (t + 1 < ntiles);
        const int kbh = KBH(t & 1), kbl = kbh + KTILE;
        const int nbh = KBH((t + 1) & 1), nbl = nbh + KTILE;

        // step0: prefetch K f32(t+1)
        if (more) {
#pragma unroll
            for (int i = 0; i < 8; i++) {
                int gi = tid + i * THREADS;
                int row = gi >> 5, c4 = gi & 31;
                cp_async16(smb + KF + row * 512 + c4 * 16,
                           kb + (size_t)(kv1 + row) * HD + c4 * 4);
            }
        }
        CP_COMMIT();

        // step1: S = Q @ K^T, nt-pairs, term-major MMA order (break accum chains)
        float s[8][4];
#pragma unroll
        for (int i = 0; i < 8; i++)
#pragma unroll
            for (int j = 0; j < 4; j++) s[i][j] = 0.0f;

#pragma unroll
        for (int kcp = 0; kcp < 4; kcp++) {
            const int kc = 2 * kcp;
#pragma unroll
            for (int ntg = 0; ntg < 4; ntg++) {
                const int nt0 = 2 * ntg, nt1 = nt0 + 1;
                if (kcp < 2)   // embedded V(t) f32->bf16 conversion (8 rows/warp/tile)
                    conv_row(smem, VF, VBH, VBL, wid * 8 + kcp * 4 + ntg, lane);
                const uint32_t rb0 = (uint32_t)(nt0 * 8 + (lane & 7)) * KROW
                                   + ((lane >> 3) << 4) + kcp * 64;
                const uint32_t rb1 = rb0 + 8 * KROW;
                uint32_t h0[4], l0[4], h1[4], l1[4];
                ldsm_x4(smb + kbh + rb0, h0[0], h0[1], h0[2], h0[3]);
                ldsm_x4(smb + kbl + rb0, l0[0], l0[1], l0[2], l0[3]);
                ldsm_x4(smb + kbh + rb1, h1[0], h1[1], h1[2], h1[3]);
                ldsm_x4(smb + kbl + rb1, l1[0], l1[1], l1[2], l1[3]);
                // kc: term-major, alternating accumulators
                mma_bf16(s[nt0], qh[kc], h0[0], h0[1]);
                mma_bf16(s[nt1], qh[kc], h1[0], h1[1]);
                mma_bf16(s[nt0], qh[kc], l0[0], l0[1]);
                mma_bf16(s[nt1], qh[kc], l1[0], l1[1]);
                mma_bf16(s[nt0], ql[kc], h0[0], h0[1]);
                mma_bf16(s[nt1], ql[kc], h1[0], h1[1]);
                // kc+1
                mma_bf16(s[nt0], qh[kc + 1], h0[2], h0[3]);
                mma_bf16(s[nt1], qh[kc + 1], h1[2], h1[3]);
                mma_bf16(s[nt0], qh[kc + 1], l0[2], l0[3]);
                mma_bf16(s[nt1], qh[kc + 1], l1[2], l1[3]);
                mma_bf16(s[nt0], ql[kc + 1], h0[2], h0[3]);
                mma_bf16(s[nt1], ql[kc + 1], h1[2], h1[3]);
            }
        }

        // step2: softmax (fixed-shift), mask from smem
        {
            const int  lim0 = PREFIX + q0 + wq + g - kv0;
            const int  lim1 = lim0 + 8;
            const bool dg   = (t >= ntiles - 2);
            const float* mrow0 = msf + (wq + g) * 64;
            const float* mrow1 = mrow0 + 8 * 64;
#pragma unroll
            for (int nt = 0; nt < 8; nt++) {
                const int c = nt * 8 + t2 * 2;
                float2 m0 = *(const float2*)(mrow0 + c);
                float2 m1 = *(const float2*)(mrow1 + c);
                float z00 = fmaf(s[nt][0] + m0.x, LOG2E, zb);
                float z01 = fmaf(s[nt][1] + m0.y, LOG2E, zb);
                float z10 = fmaf(s[nt][2] + m1.x, LOG2E, zb);
                float z11 = fmaf(s[nt][3] + m1.y, LOG2E, zb);
                if (dg) {
                    if (c     > lim0) z00 = -127.0f;
                    if (c + 1 > lim0) z01 = -127.0f;
                    if (c     > lim1) z10 = -127.0f;
                    if (c + 1 > lim1) z11 = -127.0f;
                }
                float p00 = ex2f(z00), p01 = ex2f(z01);
                float p10 = ex2f(z10), p11 = ex2f(z11);
                ls0 += p00 + p01;
                ls1 += p10 + p11;
                s[nt][0] = p00; s[nt][1] = p01; s[nt][2] = p10; s[nt][3] = p11;
            }
        }

        // step3: all warps done with V f32(t) chunks + mask(t)
        __syncthreads();

        // step4: prefetch V f32(t+1) + mask(t+1)
        if (more) {
#pragma unroll
            for (int i = 0; i < 8; i++) {
                int gi = tid + i * THREADS;
                int row = gi >> 5, c4 = gi & 31;
                cp_async16(smb + VF + row * 512 + c4 * 16,
                           vb + (size_t)(kv1 + row) * HD + c4 * 4);
            }
#pragma unroll
            for (int i = 0; i < 8; i++) {
                int gi = tid + i * THREADS;
                int row = gi >> 4, c4 = gi & 15;
                cp_async16(smb + MS + row * 256 + c4 * 16,
                           Mg + (size_t)(q0 + row) * NKV + kv1 + c4 * 4);
            }
        }
        CP_COMMIT();

        // step5/6: K f32(t+1) arrived; publish
        CP_WAIT(1);
        __syncthreads();

        // step7: O += P @ V, ntp-pairs, term-major order over 4 accumulators
#pragma unroll
        for (int kc = 0; kc < 4; kc++) {
            if (more) {
                conv_row(smem, KF, nbh, nbl, wid * 8 + kc * 2,     lane);
                conv_row(smem, KF, nbh, nbl, wid * 8 + kc * 2 + 1, lane);
            }
            uint32_t ah[4], al[4];
            split2(s[2 * kc][0],     s[2 * kc][1],     ah[0], al[0]);
            split2(s[2 * kc][2],     s[2 * kc][3],     ah[1], al[1]);
            split2(s[2 * kc + 1][0], s[2 * kc + 1][1], ah[2], al[2]);
            split2(s[2 * kc + 1][2], s[2 * kc + 1][3], ah[3], al[3]);
            const uint32_t rv = (uint32_t)(kc * 16 + ((lane >> 3) & 1) * 8 + (lane & 7)) * KROW
                              + ((lane >> 4) << 4);
#pragma unroll
            for (int pg = 0; pg < 4; pg++) {
                const int p0 = 2 * pg, p1 = p0 + 1;
                uint32_t vh0[4], vl0[4], vh1[4], vl1[4];
                ldsm_x4_t(smb + VBH + rv + p0 * 32, vh0[0], vh0[1], vh0[2], vh0[3]);
                ldsm_x4_t(smb + VBL + rv + p0 * 32, vl0[0], vl0[1], vl0[2], vl0[3]);
                ldsm_x4_t(smb + VBH + rv + p1 * 32, vh1[0], vh1[1], vh1[2], vh1[3]);
                ldsm_x4_t(smb + VBL + rv + p1 * 32, vl1[0], vl1[1], vl1[2], vl1[3]);
                // term ah*vh over 4 accumulators
                mma_bf16(o[2 * p0],     ah, vh0[0], vh0[1]);
                mma_bf16(o[2 * p0 + 1], ah, vh0[2], vh0[3]);
                mma_bf16(o[2 * p1],     ah, vh1[0], vh1[1]);
                mma_bf16(o[2 * p1 + 1], ah, vh1[2], vh1[3]);
                // term ah*vl
                mma_bf16(o[2 * p0],     ah, vl0[0], vl0[1]);
                mma_bf16(o[2 * p0 + 1], ah, vl0[2], vl0[3]);
                mma_bf16(o[2 * p1],     ah, vl1[0], vl1[1]);
                mma_bf16(o[2 * p1 + 1], ah, vl1[2], vl1[3]);
                // term al*vh
                mma_bf16(o[2 * p0],     al, vh0[0], vh0[1]);
                mma_bf16(o[2 * p0 + 1], al, vh0[2], vh0[3]);
                mma_bf16(o[2 * p1],     al, vh1[0], vh1[1]);
                mma_bf16(o[2 * p1 + 1], al, vh1[2], vh1[3]);
            }
        }

        // step8/9: V+mask(t+1) arrived; close tile
        CP_WAIT(0);
        __syncthreads();
    }

    // ---- epilogue ----
    ls0 += __shfl_xor_sync(0xffffffffu, ls0, 1);
    ls0 += __shfl_xor_sync(0xffffffffu, ls0, 2);
    ls1 += __shfl_xor_sync(0xffffffffu, ls1, 1);
    ls1 += __shfl_xor_sync(0xffffffffu, ls1, 2);
    const float i0 = 1.0f / ls0;
    const float i1 = 1.0f / ls1;

    float* ob = Og + ((size_t)h * NQ + q0 + wq) * HD;
#pragma unroll
    for (int nt = 0; nt < 16; nt++) {
        const int c = nt * 8 + t2 * 2;
        float2 w0 = make_float2(o[nt][0] * i0, o[nt][1] * i0);
        float2 w1 = make_float2(o[nt][2] * i1, o[nt][3] * i1);
        *(float2*)(ob + (size_t)g * HD + c)       = w0;
        *(float2*)(ob + (size_t)(g + 8) * HD + c) = w1;
    }
}

extern "C" void kernel_launch(void* const* d_in, const int* in_sizes, int n_in,
                              void* d_out, int out_size)
{
    const float* q = (const float*)d_in[0];
    const float* k = (const float*)d_in[1];
    const float* v = (const float*)d_in[2];
    const float* m = (const float*)d_in[3];
    float* o = (float*)d_out;

    cudaFuncSetAttribute(fsdpa_mma, cudaFuncAttributeMaxDynamicSharedMemorySize, SMEM_BYTES);
    dim3 grid(NQ / BQ, NH);
    fsdpa_mma<<<grid, THREADS, SMEM_BYTES>>>(q, k, v, m, o);
}

// round 8
// speedup vs baseline: 1.3446x; 1.0411x over previous
#include <cuda_runtime.h>
#include <cuda_bf16.h>
#include <cstdint>

// ======================= constants =======================
#define NH      16
#define NQ      4096
#define NKV     8192
#define HD      128
#define PREFIX  (NKV - NQ)
#define BQ      128
#define BK      64
#define THREADS 256
#define LOG2E   1.4426950408889634f
#define SOFT_C  10.0f

#define KVELEMS (NH * NKV * HD)        // 16,777,216 per tensor

// bf16 tiles: 64 rows x 128 elems, row stride 272B (+16B pad, ldsm conflict-free)
#define KROW    272
#define KTILE   17408                  // 64*272
// smem layout (bytes), all double buffered
#define KB(b)   ((b) * 34816)          // K hi+lo          [0, 69632)
#define VB(b)   (69632 + (b) * 34816)  // V hi+lo          [69632, 139264)
#define MSB(b)  (139264 + (b) * 32768) // mask f32         [139264, 204800)
#define SMEM_BYTES 204800
// Q staging scratch (prologue only; disjoint from tile-0 targets KB(0)/VB(0)/MSB(0))
#define QSH     VB(1)
#define QSL     KB(1)

// ======================= persistent bf16 hi/lo copies of K and V =======================
__device__ __align__(16) __nv_bfloat16 g_kh[KVELEMS];
__device__ __align__(16) __nv_bfloat16 g_kl[KVELEMS];
__device__ __align__(16) __nv_bfloat16 g_vh[KVELEMS];
__device__ __align__(16) __nv_bfloat16 g_vl[KVELEMS];

// ======================= PTX helpers (base ISA only) =======================
__device__ __forceinline__ uint32_t smem_to_u32(const void* p) {
    uint32_t a;
    asm("{ .reg .u64 t; cvta.to.shared.u64 t, %1; cvt.u32.u64 %0, t; }" : "=r"(a) : "l"(p));
    return a;
}
__device__ __forceinline__ void ldsm_x4(uint32_t addr, uint32_t& r0, uint32_t& r1,
                                        uint32_t& r2, uint32_t& r3) {
    asm volatile("ldmatrix.sync.aligned.m8n8.x4.shared.b16 {%0,%1,%2,%3}, [%4];"
                 : "=r"(r0), "=r"(r1), "=r"(r2), "=r"(r3) : "r"(addr));
}
__device__ __forceinline__ void ldsm_x4_t(uint32_t addr, uint32_t& r0, uint32_t& r1,
                                          uint32_t& r2, uint32_t& r3) {
    asm volatile("ldmatrix.sync.aligned.m8n8.x4.trans.shared.b16 {%0,%1,%2,%3}, [%4];"
                 : "=r"(r0), "=r"(r1), "=r"(r2), "=r"(r3) : "r"(addr));
}
__device__ __forceinline__ void mma_bf16(float* c, const uint32_t* a, uint32_t b0, uint32_t b1) {
    asm volatile("mma.sync.aligned.m16n8k16.row.col.f32.bf16.bf16.f32 "
                 "{%0,%1,%2,%3}, {%4,%5,%6,%7}, {%8,%9}, {%0,%1,%2,%3};"
                 : "+f"(c[0]), "+f"(c[1]), "+f"(c[2]), "+f"(c[3])
                 : "r"(a[0]), "r"(a[1]), "r"(a[2]), "r"(a[3]), "r"(b0), "r"(b1));
}
__device__ __forceinline__ uint32_t packbf(float lo, float hi) {
    uint32_t r;
    asm("cvt.rn.bf16x2.f32 %0, %1, %2;" : "=r"(r) : "f"(hi), "f"(lo));
    return r;
}
__device__ __forceinline__ float ex2f(float x) {
    float r; asm("ex2.approx.f32 %0, %1;" : "=f"(r) : "f"(x)); return r;
}
__device__ __forceinline__ void split2(float a, float b, uint32_t& hi, uint32_t& lo) {
    hi = packbf(a, b);
    float fa = __uint_as_float(hi << 16);
    float fb = __uint_as_float(hi & 0xffff0000u);
    lo = packbf(a - fa, b - fb);
}
__device__ __forceinline__ void cp_async16(uint32_t dst, const void* src) {
    asm volatile("cp.async.cg.shared.global [%0], [%1], 16;" :: "r"(dst), "l"(src) : "memory");
}
#define CP_COMMIT() asm volatile("cp.async.commit_group;" ::: "memory")
#define CP_WAIT(n)  asm volatile("cp.async.wait_group %0;" :: "n"(n) : "memory")

// ======================= prep kernel: K/V f32 -> bf16 hi/lo =======================
__global__ void __launch_bounds__(256)
prep_kernel(const float* __restrict__ K, const float* __restrict__ V)
{
    const size_t n4 = KVELEMS / 4;
    size_t i = (size_t)blockIdx.x * 256 + threadIdx.x;   // one float4 per thread
    const float* src;
    __nv_bfloat16 *dh, *dl;
    size_t j;
    if (i < n4) { src = K; dh = g_kh; dl = g_kl; j = i; }
    else        { src = V; dh = g_vh; dl = g_vl; j = i - n4; }
    float4 v = ((const float4*)src)[j];
    uint32_t h01, l01, h23, l23;
    split2(v.x, v.y, h01, l01);
    split2(v.z, v.w, h23, l23);
    ((uint2*)dh)[j] = make_uint2(h01, h23);
    ((uint2*)dl)[j] = make_uint2(l01, l23);
}

// prefetch one 64x128 bf16 tile (256B rows) into padded smem (272B rows)
__device__ __forceinline__ void fetch_bf16_tile(uint32_t smdst, const __nv_bfloat16* gsrc, int tid) {
#pragma unroll
    for (int i = 0; i < 4; i++) {
        int gi  = tid + i * THREADS;       // 0..1023
        int row = gi >> 4, c = gi & 15;    // 16B chunks per 256B row
        cp_async16(smdst + row * KROW + c * 16, gsrc + (size_t)row * HD + c * 8);
    }
}

// ======================= main kernel =======================
__global__ void __launch_bounds__(THREADS, 1)
fsdpa_mma(const float* __restrict__ Qg, const float* __restrict__ Mg,
          float* __restrict__ Og)
{
    extern __shared__ char smem[];
    const uint32_t smb = smem_to_u32(smem);
    const int tid  = threadIdx.x;
    const int lane = tid & 31;
    const int wid  = tid >> 5;
    const int g    = lane >> 2;
    const int t2   = lane & 3;
    const int h    = blockIdx.y;
    const int q0   = (int)(gridDim.x - 1 - blockIdx.x) * BQ;  // longest work first
    const int wq   = wid * 16;

    const size_t kvbase = (size_t)h * NKV * HD;
    const int ntiles = (PREFIX + q0 + BQ) / BK;

    // ---- prefetch tile 0 (K,V bf16 hi/lo + mask) into buffer 0 ----
    fetch_bf16_tile(smb + KB(0),         g_kh + kvbase, tid);
    fetch_bf16_tile(smb + KB(0) + KTILE, g_kl + kvbase, tid);
    fetch_bf16_tile(smb + VB(0),         g_vh + kvbase, tid);
    fetch_bf16_tile(smb + VB(0) + KTILE, g_vl + kvbase, tid);
#pragma unroll
    for (int i = 0; i < 8; i++) {
        int gi = tid + i * THREADS;
        int row = gi >> 4, c4 = gi & 15;
        cp_async16(smb + MSB(0) + row * 256 + c4 * 16, Mg + (size_t)(q0 + row) * NKV + c4 * 4);
    }
    CP_COMMIT();

    // ---- stage Q (scale folded) into scratch (buffer-1 regions), ldmatrix to regs ----
    {
        const float scale = 0.08838834764831845f;   // 1/sqrt(128)
        const float* qb = Qg + ((size_t)h * NQ + q0) * HD;
#pragma unroll
        for (int i = 0; i < 16; i++) {
            int gi  = tid + i * THREADS;
            int row = gi >> 5, c4 = (gi & 31) << 2;
            float4 v = *(const float4*)(qb + (size_t)row * HD + c4);
            v.x *= scale; v.y *= scale; v.z *= scale; v.w *= scale;
            uint32_t h01, l01, h23, l23;
            split2(v.x, v.y, h01, l01);
            split2(v.z, v.w, h23, l23);
            int off = row * KROW + c4 * 2;
            *(uint2*)(smem + QSH + off) = make_uint2(h01, h23);
            *(uint2*)(smem + QSL + off) = make_uint2(l01, l23);
        }
    }
    __syncthreads();

    uint32_t qh[8][4], ql[8][4];
    {
        const int mi = lane >> 3;
        const uint32_t ro = (uint32_t)(wq + (lane & 7) + ((mi & 1) << 3)) * KROW + ((mi >> 1) << 4);
#pragma unroll
        for (int kc = 0; kc < 8; kc++) {
            ldsm_x4(smb + QSH + ro + kc * 32, qh[kc][0], qh[kc][1], qh[kc][2], qh[kc][3]);
            ldsm_x4(smb + QSL + ro + kc * 32, ql[kc][0], ql[kc][1], ql[kc][2], ql[kc][3]);
        }
    }
    // NOTE: buffer-1 regions become free for tile-1 prefetch only after all warps
    // finish the ldsm above; the __syncthreads at loop top (t=0) provides that.

    float o[16][4];
#pragma unroll
    for (int i = 0; i < 16; i++)
#pragma unroll
        for (int j = 0; j < 4; j++) o[i][j] = 0.0f;
    float ls0 = 0.0f, ls1 = 0.0f;

    const float zb = -SOFT_C * LOG2E;

    for (int t = 0; t < ntiles; t++) {
        const int kv0 = t * BK;
        const int buf = t & 1;
        const int kbh = KB(buf), kbl = kbh + KTILE;
        const int vbh = VB(buf), vbl = vbh + KTILE;
        const float* msf = (const float*)(smem + MSB(buf));

        // tile t data arrived; all warps done with buffer buf^1 (previous tile)
        CP_WAIT(0);
        __syncthreads();

        // prefetch tile t+1 into buffer buf^1
        if (t + 1 < ntiles) {
            const size_t nb = kvbase + (size_t)(kv0 + BK) * HD;
            fetch_bf16_tile(smb + KB(buf ^ 1),         g_kh + nb, tid);
            fetch_bf16_tile(smb + KB(buf ^ 1) + KTILE, g_kl + nb, tid);
            fetch_bf16_tile(smb + VB(buf ^ 1),         g_vh + nb, tid);
            fetch_bf16_tile(smb + VB(buf ^ 1) + KTILE, g_vl + nb, tid);
#pragma unroll
            for (int i = 0; i < 8; i++) {
                int gi = tid + i * THREADS;
                int row = gi >> 4, c4 = gi & 15;
                cp_async16(smb + MSB(buf ^ 1) + row * 256 + c4 * 16,
                           Mg + (size_t)(q0 + row) * NKV + (kv0 + BK) + c4 * 4);
            }
        }
        CP_COMMIT();

        // ---- S = Q @ K^T, nt-pairs, term-major MMA order ----
        float s[8][4];
#pragma unroll
        for (int i = 0; i < 8; i++)
#pragma unroll
            for (int j = 0; j < 4; j++) s[i][j] = 0.0f;

#pragma unroll
        for (int kcp = 0; kcp < 4; kcp++) {
            const int kc = 2 * kcp;
#pragma unroll
            for (int ntg = 0; ntg < 4; ntg++) {
                const int nt0 = 2 * ntg, nt1 = nt0 + 1;
                const uint32_t rb0 = (uint32_t)(nt0 * 8 + (lane & 7)) * KROW
                                   + ((lane >> 3) << 4) + kcp * 64;
                const uint32_t rb1 = rb0 + 8 * KROW;
                uint32_t h0[4], l0[4], h1[4], l1[4];
                ldsm_x4(smb + kbh + rb0, h0[0], h0[1], h0[2], h0[3]);
                ldsm_x4(smb + kbl + rb0, l0[0], l0[1], l0[2], l0[3]);
                ldsm_x4(smb + kbh + rb1, h1[0], h1[1], h1[2], h1[3]);
                ldsm_x4(smb + kbl + rb1, l1[0], l1[1], l1[2], l1[3]);
                mma_bf16(s[nt0], qh[kc], h0[0], h0[1]);
                mma_bf16(s[nt1], qh[kc], h1[0], h1[1]);
                mma_bf16(s[nt0], qh[kc], l0[0], l0[1]);
                mma_bf16(s[nt1], qh[kc], l1[0], l1[1]);
                mma_bf16(s[nt0], ql[kc], h0[0], h0[1]);
                mma_bf16(s[nt1], ql[kc], h1[0], h1[1]);
                mma_bf16(s[nt0], qh[kc + 1], h0[2], h0[3]);
                mma_bf16(s[nt1], qh[kc + 1], h1[2], h1[3]);
                mma_bf16(s[nt0], qh[kc + 1], l0[2], l0[3]);
                mma_bf16(s[nt1], qh[kc + 1], l1[2], l1[3]);
                mma_bf16(s[nt0], ql[kc + 1], h0[2], h0[3]);
                mma_bf16(s[nt1], ql[kc + 1], h1[2], h1[3]);
            }
        }

        // ---- softmax (fixed shift) ----
        {
            const int  lim0 = PREFIX + q0 + wq + g - kv0;
            const int  lim1 = lim0 + 8;
            const bool dg   = (t >= ntiles - 2);
            const float* mrow0 = msf + (wq + g) * 64;
            const float* mrow1 = mrow0 + 8 * 64;
#pragma unroll
            for (int nt = 0; nt < 8; nt++) {
                const int c = nt * 8 + t2 * 2;
                float2 m0 = *(const float2*)(mrow0 + c);
                float2 m1 = *(const float2*)(mrow1 + c);
                float z00 = fmaf(s[nt][0] + m0.x, LOG2E, zb);
                float z01 = fmaf(s[nt][1] + m0.y, LOG2E, zb);
                float z10 = fmaf(s[nt][2] + m1.x, LOG2E, zb);
                float z11 = fmaf(s[nt][3] + m1.y, LOG2E, zb);
                if (dg) {
                    if (c     > lim0) z00 = -127.0f;
                    if (c + 1 > lim0) z01 = -127.0f;
                    if (c     > lim1) z10 = -127.0f;
                    if (c + 1 > lim1) z11 = -127.0f;
                }
                float p00 = ex2f(z00), p01 = ex2f(z01);
                float p10 = ex2f(z10), p11 = ex2f(z11);
                ls0 += p00 + p01;
                ls1 += p10 + p11;
                s[nt][0] = p00; s[nt][1] = p01; s[nt][2] = p10; s[nt][3] = p11;
            }
        }

        // ---- O += P @ V, ntp-pairs, term-major over 4 accumulators ----
#pragma unroll
        for (int kc = 0; kc < 4; kc++) {
            uint32_t ah[4], al[4];
            split2(s[2 * kc][0],     s[2 * kc][1],     ah[0], al[0]);
            split2(s[2 * kc][2],     s[2 * kc][3],     ah[1], al[1]);
            split2(s[2 * kc + 1][0], s[2 * kc + 1][1], ah[2], al[2]);
            split2(s[2 * kc + 1][2], s[2 * kc + 1][3], ah[3], al[3]);
            const uint32_t rv = (uint32_t)(kc * 16 + ((lane >> 3) & 1) * 8 + (lane & 7)) * KROW
                              + ((lane >> 4) << 4);
#pragma unroll
            for (int pg = 0; pg < 4; pg++) {
                const int p0 = 2 * pg, p1 = p0 + 1;
                uint32_t vh0[4], vl0[4], vh1[4], vl1[4];
                ldsm_x4_t(smb + vbh + rv + p0 * 32, vh0[0], vh0[1], vh0[2], vh0[3]);
                ldsm_x4_t(smb + vbl + rv + p0 * 32, vl0[0], vl0[1], vl0[2], vl0[3]);
                ldsm_x4_t(smb + vbh + rv + p1 * 32, vh1[0], vh1[1], vh1[2], vh1[3]);
                ldsm_x4_t(smb + vbl + rv + p1 * 32, vl1[0], vl1[1], vl1[2], vl1[3]);
                mma_bf16(o[2 * p0],     ah, vh0[0], vh0[1]);
                mma_bf16(o[2 * p0 + 1], ah, vh0[2], vh0[3]);
                mma_bf16(o[2 * p1],     ah, vh1[0], vh1[1]);
                mma_bf16(o[2 * p1 + 1], ah, vh1[2], vh1[3]);
                mma_bf16(o[2 * p0],     ah, vl0[0], vl0[1]);
                mma_bf16(o[2 * p0 + 1], ah, vl0[2], vl0[3]);
                mma_bf16(o[2 * p1],     ah, vl1[0], vl1[1]);
                mma_bf16(o[2 * p1 + 1], ah, vl1[2], vl1[3]);
                mma_bf16(o[2 * p0],     al, vh0[0], vh0[1]);
                mma_bf16(o[2 * p0 + 1], al, vh0[2], vh0[3]);
                mma_bf16(o[2 * p1],     al, vh1[0], vh1[1]);
                mma_bf16(o[2 * p1 + 1], al, vh1[2], vh1[3]);
            }
        }
    }

    // ---- epilogue ----
    ls0 += __shfl_xor_sync(0xffffffffu, ls0, 1);
    ls0 += __shfl_xor_sync(0xffffffffu, ls0, 2);
    ls1 += __shfl_xor_sync(0xffffffffu, ls1, 1);
    ls1 += __shfl_xor_sync(0xffffffffu, ls1, 2);
    const float i0 = 1.0f / ls0;
    const float i1 = 1.0f / ls1;

    float* ob = Og + ((size_t)h * NQ + q0 + wq) * HD;
#pragma unroll
    for (int nt = 0; nt < 16; nt++) {
        const int c = nt * 8 + t2 * 2;
        float2 w0 = make_float2(o[nt][0] * i0, o[nt][1] * i0);
        float2 w1 = make_float2(o[nt][2] * i1, o[nt][3] * i1);
        *(float2*)(ob + (size_t)g * HD + c)       = w0;
        *(float2*)(ob + (size_t)(g + 8) * HD + c) = w1;
    }
}

extern "C" void kernel_launch(void* const* d_in, const int* in_sizes, int n_in,
                              void* d_out, int out_size)
{
    const float* q = (const float*)d_in[0];
    const float* k = (const float*)d_in[1];
    const float* v = (const float*)d_in[2];
    const float* m = (const float*)d_in[3];
    float* o = (float*)d_out;

    // 1) convert K/V to bf16 hi/lo persistent scratch
    prep_kernel<<<2 * (KVELEMS / 4) / 256, 256>>>(k, v);

    // 2) attention
    cudaFuncSetAttribute(fsdpa_mma, cudaFuncAttributeMaxDynamicSharedMemorySize, SMEM_BYTES);
    dim3 grid(NQ / BQ, NH);
    fsdpa_mma<<<grid, THREADS, SMEM_BYTES>>>(q, m, o);
}